// round 12
// baseline (speedup 1.0000x reference)
#include <cuda_runtime.h>
#include <math.h>

#define BATCH   8192
#define NNODES  32
#define DIM     128
#define KDIM    384    // 3*128

// ---- scratch (no allocation allowed) ----
__device__ float g_G[BATCH * KDIM];       // (B, 3*128) weighted feature sums
__device__ float g_P[3 * BATCH * DIM];    // split-K partials
__device__ float g_wab[12 * DIM];         // rows 0..8: wtop[i*3+j], rows 9..11: wbot[j]
__device__ float g_wb01[2 * DIM];         // interleaved (wbot0[d], wbot1[d]) pairs
__device__ int   g_mask_mode;             // 0=bool/u8, 1=int32, 2=float32

__device__ __forceinline__ float2 ffma2(float2 a, float2 b, float2 c) {
    float2 d;
    asm("{\n\t"
        ".reg .b64 ra, rb, rc, rd;\n\t"
        "mov.b64 ra, {%2,%3};\n\t"
        "mov.b64 rb, {%4,%5};\n\t"
        "mov.b64 rc, {%6,%7};\n\t"
        "fma.rn.f32x2 rd, ra, rb, rc;\n\t"
        "mov.b64 {%0,%1}, rd;\n\t"
        "}"
        : "=f"(d.x), "=f"(d.y)
        : "f"(a.x), "f"(a.y), "f"(b.x), "f"(b.y), "f"(c.x), "f"(c.y));
    return d;
}

// ============================================================
// Kernel 0: blocks 0..23 = weight prep (16 rows each),
//           block 24 = mask sniff
// ============================================================
__global__ __launch_bounds__(256) void prep_detect_kernel(const unsigned int* __restrict__ m,
                                                          const float* __restrict__ W,
                                                          const float* __restrict__ a) {
    if (blockIdx.x == 24) {
        __shared__ int sF, sG;
        if (threadIdx.x == 0) { sF = 0; sG = 0; }
        __syncthreads();
        int f = 0, g = 0;
        #pragma unroll
        for (int r = 0; r < 8; r++) {
            unsigned v = m[r * 256 + threadIdx.x];
            if (v == 0x3F800000u) f = 1;
            else if (v > 1u)      g = 1;
        }
        if (f) atomicOr(&sF, 1);
        if (g) atomicOr(&sG, 1);
        __syncthreads();
        if (threadIdx.x == 0) g_mask_mode = sF ? 2 : (sG ? 0 : 1);
        return;
    }

    const int i    = blockIdx.x >> 3;       // type 0..2
    const int oct  = blockIdx.x & 7;        // 16-row slice
    const int wid  = threadIdx.x >> 5;      // 8 warps
    const int lane = threadIdx.x & 31;

    const float4 at0 = *(const float4*)&a[0 * 256 + lane * 4];
    const float4 at1 = *(const float4*)&a[1 * 256 + lane * 4];
    const float4 at2 = *(const float4*)&a[2 * 256 + lane * 4];
    const float4 ab  = *(const float4*)&a[i * 256 + 128 + lane * 4];

    float4 wv[2];
    #pragma unroll
    for (int r = 0; r < 2; r++) {
        int d = oct * 16 + r * 8 + wid;
        wv[r] = *(const float4*)&W[(size_t)i * (DIM * DIM) + (size_t)d * DIM + lane * 4];
    }

    #pragma unroll
    for (int r = 0; r < 2; r++) {
        int d = oct * 16 + r * 8 + wid;
        float4 x = wv[r];
        float s0 = x.x * at0.x + x.y * at0.y + x.z * at0.z + x.w * at0.w;
        float s1 = x.x * at1.x + x.y * at1.y + x.z * at1.z + x.w * at1.w;
        float s2 = x.x * at2.x + x.y * at2.y + x.z * at2.z + x.w * at2.w;
        float sb = x.x * ab.x  + x.y * ab.y  + x.z * ab.z  + x.w * ab.w;
        #pragma unroll
        for (int off = 16; off > 0; off >>= 1) {
            s0 += __shfl_xor_sync(0xFFFFFFFFu, s0, off);
            s1 += __shfl_xor_sync(0xFFFFFFFFu, s1, off);
            s2 += __shfl_xor_sync(0xFFFFFFFFu, s2, off);
            sb += __shfl_xor_sync(0xFFFFFFFFu, sb, off);
        }
        if (lane == 0) {
            g_wab[(i * 3 + 0) * DIM + d] = s0;
            g_wab[(i * 3 + 1) * DIM + d] = s1;
            g_wab[(i * 3 + 2) * DIM + d] = s2;
            g_wab[(9 + i) * DIM + d]     = sb;
            if (i == 0)      g_wb01[2 * d]     = sb;
            else if (i == 1) g_wb01[2 * d + 1] = sb;
        }
    }
}

// ============================================================
// Kernel 1: attention -> G.  128 threads = 1 batch, grid 8192.
//   Unnormalized-softmax single pass (exp range fp32-safe):
//     p_jn = exp(sb_jn) masked; A_j = sum_n p_jn h_n (registers)
//     E_j  = sum_i exp(ls_ij); Z_g = sum_j E_j S_gj
//     G_j  = (E_j/Z_g per group) A_j + mask_self_j * h0
//   Warp->node map: node = w*8+v (warps 0,1 ally; 2,3 opp).
//   All float4-accessed shared arrays are 16B-aligned.
// ============================================================
__global__ __launch_bounds__(128) void attn_kernel(const float* __restrict__ hptr,
                                                   const void*  __restrict__ maskp) {
    __shared__ __align__(16) float part_sh[4][3][DIM];   // per-warp partial A
    __shared__ __align__(16) float h0_sh[DIM];           // node-0 features
    __shared__ __align__(16) float mk_sh[3][32];
    __shared__ __align__(16) float S_sh[4][4];           // per-warp group sums (padded)
    __shared__ __align__(16) float E_sh[4];              // padded

    const int t    = threadIdx.x;
    const int w    = t >> 5;
    const int lane = t & 31;
    const int b    = blockIdx.x;

    const float4 wpA = *(const float4*)&g_wb01[lane * 8];       // (wb0,wb1) f0,f1
    const float4 wpB = *(const float4*)&g_wb01[lane * 8 + 4];   // (wb0,wb1) f2,f3
    const float4 wb2 = *(const float4*)&g_wab[11 * DIM + lane * 4];

    // prefetch this warp's 8 nodes (node = w*8+v), coalesced 512B/warp
    const float4* hp = (const float4*)(hptr + (size_t)b * (NNODES * DIM));
    float4 xs[8];
    #pragma unroll
    for (int v = 0; v < 8; v++) xs[v] = hp[(w * 8 + v) * 32 + lane];

    // mask (3 x 32), normalized to {0,1}
    if (t < 96) {
        int j = t >> 5, node = t & 31;
        size_t idx = (size_t)j * (BATCH * NNODES) + (size_t)b * NNODES + node;
        int mode = g_mask_mode;
        float mv;
        if (mode == 0)      mv = ((const unsigned char*)maskp)[idx] ? 1.f : 0.f;
        else if (mode == 1) mv = ((const int*)maskp)[idx] ? 1.f : 0.f;
        else                mv = (((const float*)maskp)[idx] != 0.f) ? 1.f : 0.f;
        mk_sh[j][node] = mv;
    }
    __syncthreads();    // mk_sh ready

    // ---- single pass: logits -> p -> A accumulation ----
    float4 a0 = make_float4(0.f, 0.f, 0.f, 0.f);
    float4 a1 = a0, a2 = a0;
    float S0 = 0.f, S1 = 0.f, S2 = 0.f;

    #pragma unroll
    for (int v = 0; v < 8; v++) {
        const int node = w * 8 + v;
        float4 x = xs[v];
        if (w == 0 && v == 0) {
            *(float4*)&h0_sh[lane * 4] = x;     // self node: stage only
            continue;
        }
        float2 d01 = make_float2(0.f, 0.f);
        d01 = ffma2(make_float2(x.x, x.x), make_float2(wpA.x, wpA.y), d01);
        d01 = ffma2(make_float2(x.y, x.y), make_float2(wpA.z, wpA.w), d01);
        d01 = ffma2(make_float2(x.z, x.z), make_float2(wpB.x, wpB.y), d01);
        d01 = ffma2(make_float2(x.w, x.w), make_float2(wpB.z, wpB.w), d01);
        float d2 = x.x * wb2.x + x.y * wb2.y + x.z * wb2.z + x.w * wb2.w;
        #pragma unroll
        for (int off = 16; off > 0; off >>= 1) {
            d01.x += __shfl_xor_sync(0xFFFFFFFFu, d01.x, off);
            d01.y += __shfl_xor_sync(0xFFFFFFFFu, d01.y, off);
            d2    += __shfl_xor_sync(0xFFFFFFFFu, d2,    off);
        }
        // masked p (mask true -> exclude)
        float p0 = (mk_sh[0][node] > 0.5f) ? 0.f : expf(d01.x);
        float p1 = (mk_sh[1][node] > 0.5f) ? 0.f : expf(d01.y);
        float p2 = (mk_sh[2][node] > 0.5f) ? 0.f : expf(d2);
        a0.x += p0 * x.x; a0.y += p0 * x.y; a0.z += p0 * x.z; a0.w += p0 * x.w;
        a1.x += p1 * x.x; a1.y += p1 * x.y; a1.z += p1 * x.z; a1.w += p1 * x.w;
        a2.x += p2 * x.x; a2.y += p2 * x.y; a2.z += p2 * x.z; a2.w += p2 * x.w;
        S0 += p0; S1 += p1; S2 += p2;
    }
    if (lane == 0) {
        S_sh[w][0] = S0; S_sh[w][1] = S1; S_sh[w][2] = S2;
    }
    __syncthreads();    // h0_sh + S_sh ready

    // ---- E_j: warp j (j<3) computes sum_i exp(ls_ij) ----
    if (w < 3) {
        const float4 x = *(const float4*)&h0_sh[lane * 4];
        float e = 0.f;
        #pragma unroll
        for (int i = 0; i < 3; i++) {
            const float4 wt = *(const float4*)&g_wab[(i * 3 + w) * DIM + lane * 4];
            float dq = x.x * wt.x + x.y * wt.y + x.z * wt.z + x.w * wt.w;
            #pragma unroll
            for (int off = 16; off > 0; off >>= 1)
                dq += __shfl_xor_sync(0xFFFFFFFFu, dq, off);
            e += expf(dq);
        }
        if (lane == 0) E_sh[w] = e;
    }
    __syncthreads();    // E_sh ready

    // ---- scale A by E_j / Z_group, write partials ----
    {
        float E0 = E_sh[0], E1 = E_sh[1], E2 = E_sh[2];
        float Sg0, Sg1, Sg2;
        if (w < 2) {    // ally group: warps 0,1
            Sg0 = S_sh[0][0] + S_sh[1][0];
            Sg1 = S_sh[0][1] + S_sh[1][1];
            Sg2 = S_sh[0][2] + S_sh[1][2];
        } else {        // opp group: warps 2,3
            Sg0 = S_sh[2][0] + S_sh[3][0];
            Sg1 = S_sh[2][1] + S_sh[3][1];
            Sg2 = S_sh[2][2] + S_sh[3][2];
        }
        float Z = E0 * Sg0 + E1 * Sg1 + E2 * Sg2;
        float inv = (Z > 0.f) ? (1.f / Z) : 0.f;
        float c0 = E0 * inv, c1 = E1 * inv, c2 = E2 * inv;
        a0.x *= c0; a0.y *= c0; a0.z *= c0; a0.w *= c0;
        a1.x *= c1; a1.y *= c1; a1.z *= c1; a1.w *= c1;
        a2.x *= c2; a2.y *= c2; a2.z *= c2; a2.w *= c2;
    }
    *(float4*)&part_sh[w][0][lane * 4] = a0;
    *(float4*)&part_sh[w][1][lane * 4] = a1;
    *(float4*)&part_sh[w][2][lane * 4] = a2;
    __syncthreads();

    // ---- cross-warp sum + self term: 96 threads, float4 wide ----
    if (t < 96) {
        int j = t >> 5;
        int c = (t & 31) * 4;
        float4 s0 = *(const float4*)&part_sh[0][j][c];
        float4 s1 = *(const float4*)&part_sh[1][j][c];
        float4 s2 = *(const float4*)&part_sh[2][j][c];
        float4 s3 = *(const float4*)&part_sh[3][j][c];
        float mk = mk_sh[j][0];
        float4 h0 = *(const float4*)&h0_sh[c];
        float4 s;
        s.x = (s0.x + s1.x) + (s2.x + s3.x) + mk * h0.x;
        s.y = (s0.y + s1.y) + (s2.y + s3.y) + mk * h0.y;
        s.z = (s0.z + s1.z) + (s2.z + s3.z) + mk * h0.z;
        s.w = (s0.w + s1.w) + (s2.w + s3.w) + mk * h0.w;
        *(float4*)(g_G + (size_t)b * KDIM + j * DIM + c) = s;
    }
}

// ============================================================
// Kernel 2: split-K GEMM.  P[j] = G_j (8192x128) @ W_j (128x128)
// ============================================================
__global__ __launch_bounds__(256) void gemm_split_kernel(const float* __restrict__ W) {
    __shared__ __align__(16) float Gst[32][68];    // [kk][row], transposed
    __shared__ __align__(16) float Ws[32][132];    // [kk][col]

    const int tid  = threadIdx.x;
    const int w    = tid >> 5;
    const int lane = tid & 31;
    const int row0 = blockIdx.x * 64;
    const int j    = blockIdx.y;

    float2 acc[8][2];
    #pragma unroll
    for (int i = 0; i < 8; i++) { acc[i][0] = make_float2(0.f, 0.f); acc[i][1] = make_float2(0.f, 0.f); }

    for (int k0 = 0; k0 < 128; k0 += 32) {
        #pragma unroll
        for (int v = 0; v < 2; v++) {                 // G 64x32 -> transposed
            int f = tid + v * 256;
            int r = f >> 3, c = (f & 7) * 4;
            float4 x = *(const float4*)(g_G + (size_t)(row0 + r) * KDIM + j * 128 + k0 + c);
            Gst[c + 0][r] = x.x; Gst[c + 1][r] = x.y; Gst[c + 2][r] = x.z; Gst[c + 3][r] = x.w;
        }
        #pragma unroll
        for (int v = 0; v < 4; v++) {                 // W 32x128
            int f = tid + v * 256;
            int r = f >> 5, c = (f & 31) * 4;
            *(float4*)&Ws[r][c] = *(const float4*)(W + (size_t)j * (DIM * DIM) + (size_t)(k0 + r) * DIM + c);
        }
        __syncthreads();

        #pragma unroll
        for (int kk = 0; kk < 32; kk++) {
            float4 bv = *(const float4*)&Ws[kk][lane * 4];
            float4 ga = *(const float4*)&Gst[kk][w * 8];        // broadcast
            float4 gb = *(const float4*)&Gst[kk][w * 8 + 4];    // broadcast
            float2 b01 = make_float2(bv.x, bv.y);
            float2 b23 = make_float2(bv.z, bv.w);
            float gs[8] = {ga.x, ga.y, ga.z, ga.w, gb.x, gb.y, gb.z, gb.w};
            #pragma unroll
            for (int i = 0; i < 8; i++) {
                float2 a2 = make_float2(gs[i], gs[i]);
                acc[i][0] = ffma2(a2, b01, acc[i][0]);
                acc[i][1] = ffma2(a2, b23, acc[i][1]);
            }
        }
        __syncthreads();
    }

    float* Pj = g_P + (size_t)j * (BATCH * DIM);
    #pragma unroll
    for (int i = 0; i < 8; i++) {
        int r = row0 + w * 8 + i;
        float4 v;
        v.x = acc[i][0].x; v.y = acc[i][0].y; v.z = acc[i][1].x; v.w = acc[i][1].y;
        *(float4*)(Pj + (size_t)r * DIM + lane * 4) = v;
    }
}

// ============================================================
// Kernel 3: out = elu(P0 + P1 + P2); 2 float4 per thread
// ============================================================
__global__ __launch_bounds__(256) void epilogue_kernel(float* __restrict__ out) {
    int i0 = (blockIdx.x * 512 + threadIdx.x) * 4;
    int i1 = i0 + 1024;
    float4 a0 = *(const float4*)(g_P + i0);
    float4 b0 = *(const float4*)(g_P + BATCH * DIM + i0);
    float4 c0 = *(const float4*)(g_P + 2 * BATCH * DIM + i0);
    float4 a1 = *(const float4*)(g_P + i1);
    float4 b1 = *(const float4*)(g_P + BATCH * DIM + i1);
    float4 c1 = *(const float4*)(g_P + 2 * BATCH * DIM + i1);
    float4 v0, v1;
    v0.x = a0.x + b0.x + c0.x;  v0.y = a0.y + b0.y + c0.y;
    v0.z = a0.z + b0.z + c0.z;  v0.w = a0.w + b0.w + c0.w;
    v1.x = a1.x + b1.x + c1.x;  v1.y = a1.y + b1.y + c1.y;
    v1.z = a1.z + b1.z + c1.z;  v1.w = a1.w + b1.w + c1.w;
    v0.x = (v0.x > 0.f) ? v0.x : expm1f(v0.x);
    v0.y = (v0.y > 0.f) ? v0.y : expm1f(v0.y);
    v0.z = (v0.z > 0.f) ? v0.z : expm1f(v0.z);
    v0.w = (v0.w > 0.f) ? v0.w : expm1f(v0.w);
    v1.x = (v1.x > 0.f) ? v1.x : expm1f(v1.x);
    v1.y = (v1.y > 0.f) ? v1.y : expm1f(v1.y);
    v1.z = (v1.z > 0.f) ? v1.z : expm1f(v1.z);
    v1.w = (v1.w > 0.f) ? v1.w : expm1f(v1.w);
    *(float4*)(out + i0) = v0;
    *(float4*)(out + i1) = v1;
}

// ============================================================
extern "C" void kernel_launch(void* const* d_in, const int* in_sizes, int n_in,
                              void* d_out, int out_size) {
    const float* h    = (const float*)d_in[0];
    const void*  mask = d_in[1];
    const float* W    = (const float*)d_in[5];
    const float* a    = (const float*)d_in[6];
    float* out = (float*)d_out;

    prep_detect_kernel<<<25, 256>>>((const unsigned int*)mask, W, a);
    attn_kernel<<<BATCH, 128>>>(h, mask);
    gemm_split_kernel<<<dim3(128, 3), 256>>>(W);
    epilogue_kernel<<<(BATCH * DIM) / 2048, 256>>>(out);
}

// round 14
// speedup vs baseline: 1.0867x; 1.0867x over previous
#include <cuda_runtime.h>
#include <math.h>

#define BATCH   8192
#define NNODES  32
#define DIM     128
#define KDIM    384    // 3*128

// ---- scratch (no allocation allowed) ----
__device__ float g_G[BATCH * KDIM];       // (B, 3*128) weighted feature sums
__device__ float g_P[3 * BATCH * DIM];    // split-K partials
__device__ float g_wab[12 * DIM];         // rows 0..8: wtop[i*3+j], rows 9..11: wbot[j]
__device__ float g_wb01[2 * DIM];         // interleaved (wbot0[d], wbot1[d]) pairs
__device__ int   g_mask_mode;             // 0=bool/u8, 1=int32, 2=float32

__device__ __forceinline__ float2 ffma2(float2 a, float2 b, float2 c) {
    float2 d;
    asm("{\n\t"
        ".reg .b64 ra, rb, rc, rd;\n\t"
        "mov.b64 ra, {%2,%3};\n\t"
        "mov.b64 rb, {%4,%5};\n\t"
        "mov.b64 rc, {%6,%7};\n\t"
        "fma.rn.f32x2 rd, ra, rb, rc;\n\t"
        "mov.b64 {%0,%1}, rd;\n\t"
        "}"
        : "=f"(d.x), "=f"(d.y)
        : "f"(a.x), "f"(a.y), "f"(b.x), "f"(b.y), "f"(c.x), "f"(c.y));
    return d;
}

// ============================================================
// Kernel 0: blocks 0..23 = weight prep (16 rows each),
//           block 24 = mask sniff
// ============================================================
__global__ __launch_bounds__(256) void prep_detect_kernel(const unsigned int* __restrict__ m,
                                                          const float* __restrict__ W,
                                                          const float* __restrict__ a) {
    if (blockIdx.x == 24) {
        __shared__ int sF, sG;
        if (threadIdx.x == 0) { sF = 0; sG = 0; }
        __syncthreads();
        int f = 0, g = 0;
        #pragma unroll
        for (int r = 0; r < 8; r++) {
            unsigned v = m[r * 256 + threadIdx.x];
            if (v == 0x3F800000u) f = 1;
            else if (v > 1u)      g = 1;
        }
        if (f) atomicOr(&sF, 1);
        if (g) atomicOr(&sG, 1);
        __syncthreads();
        if (threadIdx.x == 0) g_mask_mode = sF ? 2 : (sG ? 0 : 1);
        return;
    }

    const int i    = blockIdx.x >> 3;       // type 0..2
    const int oct  = blockIdx.x & 7;        // 16-row slice
    const int wid  = threadIdx.x >> 5;      // 8 warps
    const int lane = threadIdx.x & 31;

    const float4 at0 = *(const float4*)&a[0 * 256 + lane * 4];
    const float4 at1 = *(const float4*)&a[1 * 256 + lane * 4];
    const float4 at2 = *(const float4*)&a[2 * 256 + lane * 4];
    const float4 ab  = *(const float4*)&a[i * 256 + 128 + lane * 4];

    float4 wv[2];
    #pragma unroll
    for (int r = 0; r < 2; r++) {
        int d = oct * 16 + r * 8 + wid;
        wv[r] = *(const float4*)&W[(size_t)i * (DIM * DIM) + (size_t)d * DIM + lane * 4];
    }

    #pragma unroll
    for (int r = 0; r < 2; r++) {
        int d = oct * 16 + r * 8 + wid;
        float4 x = wv[r];
        float s0 = x.x * at0.x + x.y * at0.y + x.z * at0.z + x.w * at0.w;
        float s1 = x.x * at1.x + x.y * at1.y + x.z * at1.z + x.w * at1.w;
        float s2 = x.x * at2.x + x.y * at2.y + x.z * at2.z + x.w * at2.w;
        float sb = x.x * ab.x  + x.y * ab.y  + x.z * ab.z  + x.w * ab.w;
        #pragma unroll
        for (int off = 16; off > 0; off >>= 1) {
            s0 += __shfl_xor_sync(0xFFFFFFFFu, s0, off);
            s1 += __shfl_xor_sync(0xFFFFFFFFu, s1, off);
            s2 += __shfl_xor_sync(0xFFFFFFFFu, s2, off);
            sb += __shfl_xor_sync(0xFFFFFFFFu, sb, off);
        }
        if (lane == 0) {
            g_wab[(i * 3 + 0) * DIM + d] = s0;
            g_wab[(i * 3 + 1) * DIM + d] = s1;
            g_wab[(i * 3 + 2) * DIM + d] = s2;
            g_wab[(9 + i) * DIM + d]     = sb;
            if (i == 0)      g_wb01[2 * d]     = sb;
            else if (i == 1) g_wb01[2 * d + 1] = sb;
        }
    }
}

// ============================================================
// Kernel 1: attention -> G.  128 threads = 1 batch, grid 8192.
//   Register-resident h (best-known R7 structure), __expf.
// ============================================================
__global__ __launch_bounds__(128) void attn_kernel(const float* __restrict__ hptr,
                                                   const void*  __restrict__ maskp) {
    __shared__ __align__(16) float part_sh[4][3][DIM];   // per-warp partial G
    __shared__ __align__(16) float h0_sh[DIM];           // node-0 features
    __shared__ __align__(16) float sb8_sh[3][32][8];     // 8-lane partials per (j,node)
    __shared__ __align__(16) float mk_sh[3][32];
    __shared__ __align__(16) float4 w2n_sh[32];          // (w2_0,w2_1,w2_2,pad)/node
    __shared__ __align__(16) float E_sh[4];

    const int t    = threadIdx.x;
    const int w    = t >> 5;
    const int lane = t & 31;
    const int b    = blockIdx.x;

    const float4 wpA = *(const float4*)&g_wb01[lane * 8];
    const float4 wpB = *(const float4*)&g_wb01[lane * 8 + 4];
    const float4 wb2 = *(const float4*)&g_wab[11 * DIM + lane * 4];

    const float4* hp = (const float4*)(hptr + (size_t)b * (NNODES * DIM));
    float4 xs[8];
    #pragma unroll
    for (int v = 0; v < 8; v++) xs[v] = hp[v * 128 + t];

    if (t < 96) {
        int j = t >> 5, node = t & 31;
        size_t idx = (size_t)j * (BATCH * NNODES) + (size_t)b * NNODES + node;
        int mode = g_mask_mode;
        float mv;
        if (mode == 0)      mv = ((const unsigned char*)maskp)[idx] ? 1.f : 0.f;
        else if (mode == 1) mv = ((const int*)maskp)[idx] ? 1.f : 0.f;
        else                mv = (((const float*)maskp)[idx] != 0.f) ? 1.f : 0.f;
        mk_sh[j][node] = mv;
    }

    // ---- v-loop: neighbor logit partials (reduce to 8-lane classes) ----
    #pragma unroll
    for (int v = 0; v < 8; v++) {
        float4 x = xs[v];
        int node = v * 4 + w;
        if (v == 0 && w == 0)
            *(float4*)&h0_sh[lane * 4] = x;

        float2 d01 = make_float2(0.f, 0.f);
        d01 = ffma2(make_float2(x.x, x.x), make_float2(wpA.x, wpA.y), d01);
        d01 = ffma2(make_float2(x.y, x.y), make_float2(wpA.z, wpA.w), d01);
        d01 = ffma2(make_float2(x.z, x.z), make_float2(wpB.x, wpB.y), d01);
        d01 = ffma2(make_float2(x.w, x.w), make_float2(wpB.z, wpB.w), d01);
        float d2 = x.x * wb2.x + x.y * wb2.y + x.z * wb2.z + x.w * wb2.w;
        #pragma unroll
        for (int off = 16; off >= 8; off >>= 1) {
            d01.x += __shfl_xor_sync(0xFFFFFFFFu, d01.x, off);
            d01.y += __shfl_xor_sync(0xFFFFFFFFu, d01.y, off);
            d2    += __shfl_xor_sync(0xFFFFFFFFu, d2,    off);
        }
        if (lane < 8 && node > 0) {
            sb8_sh[0][node][lane] = d01.x;
            sb8_sh[1][node][lane] = d01.y;
            sb8_sh[2][node][lane] = d2;
        }
    }
    __syncthreads();

    // ---- phase B ----
    int   jj[2], nd[2];
    bool  act[2];
    float pv[2];
    float Sreg[3] = {0.f, 0.f, 0.f};

    if (w < 2) {
        const int NN   = (w == 0) ? 15 : 16;
        const int base = (w == 0) ? 1  : 16;
        const int NP   = 3 * NN;

        float sbv[2];
        float lm = -INFINITY;
        #pragma unroll
        for (int r = 0; r < 2; r++) {
            int p = lane + r * 32;
            bool valid = (p < NP);
            int j = valid ? (p / NN) : 0;
            int node = valid ? (base + p % NN) : base;
            jj[r] = j; nd[r] = node;
            float4 sA = *(const float4*)&sb8_sh[j][node][0];
            float4 sB = *(const float4*)&sb8_sh[j][node][4];
            sbv[r] = ((sA.x + sA.y) + (sA.z + sA.w)) + ((sB.x + sB.y) + (sB.z + sB.w));
            bool excl = (mk_sh[j][node] > 0.5f);
            act[r] = valid && !excl;
            if (act[r]) lm = fmaxf(lm, sbv[r]);
        }
        #pragma unroll
        for (int off = 16; off > 0; off >>= 1)
            lm = fmaxf(lm, __shfl_xor_sync(0xFFFFFFFFu, lm, off));

        #pragma unroll
        for (int r = 0; r < 2; r++) {
            pv[r] = 0.f;
            if (act[r]) {
                pv[r] = __expf(sbv[r] - lm);
                Sreg[jj[r]] += pv[r];
            }
        }
        #pragma unroll
        for (int off = 16; off > 0; off >>= 1) {
            Sreg[0] += __shfl_xor_sync(0xFFFFFFFFu, Sreg[0], off);
            Sreg[1] += __shfl_xor_sync(0xFFFFFFFFu, Sreg[1], off);
            Sreg[2] += __shfl_xor_sync(0xFFFFFFFFu, Sreg[2], off);
        }
    } else if (w == 2) {
        const float4 x = *(const float4*)&h0_sh[lane * 4];
        float ls[9];
        #pragma unroll
        for (int q = 0; q < 9; q++) {
            const float4 wt = *(const float4*)&g_wab[q * DIM + lane * 4];
            float dq = x.x * wt.x + x.y * wt.y + x.z * wt.z + x.w * wt.w;
            #pragma unroll
            for (int off = 16; off > 0; off >>= 1)
                dq += __shfl_xor_sync(0xFFFFFFFFu, dq, off);
            ls[q] = dq;
        }
        float ml = ls[0];
        #pragma unroll
        for (int q = 1; q < 9; q++) ml = fmaxf(ml, ls[q]);
        if (lane < 3) {
            float e = __expf(ls[0 * 3 + lane] - ml) + __expf(ls[1 * 3 + lane] - ml)
                    + __expf(ls[2 * 3 + lane] - ml);
            E_sh[lane] = e;
        }
    } else if (w == 3 && lane < 3) {
        ((float*)&w2n_sh[0])[lane] = mk_sh[lane][0];
    }
    __syncthreads();

    // ---- phase C ----
    if (w < 2) {
        float E0 = E_sh[0], E1 = E_sh[1], E2 = E_sh[2];
        float Z = E0 * Sreg[0] + E1 * Sreg[1] + E2 * Sreg[2];
        float inv = (Z > 0.f) ? (1.f / Z) : 0.f;
        float Ej[3] = {E0 * inv, E1 * inv, E2 * inv};
        #pragma unroll
        for (int r = 0; r < 2; r++) {
            int p = lane + r * 32;
            const int NP = (w == 0) ? 45 : 48;
            if (p < NP) ((float*)&w2n_sh[nd[r]])[jj[r]] = pv[r] * Ej[jj[r]];
        }
    }
    __syncthreads();

    // ---- register-resident accumulation over this thread's 8 nodes ----
    float4 a0 = make_float4(0.f, 0.f, 0.f, 0.f);
    float4 a1 = a0, a2 = a0;
    #pragma unroll
    for (int v = 0; v < 8; v++) {
        float4 wv = w2n_sh[v * 4 + w];      // LDS.128 broadcast
        float4 x = xs[v];
        a0.x += wv.x * x.x; a0.y += wv.x * x.y; a0.z += wv.x * x.z; a0.w += wv.x * x.w;
        a1.x += wv.y * x.x; a1.y += wv.y * x.y; a1.z += wv.y * x.z; a1.w += wv.y * x.w;
        a2.x += wv.z * x.x; a2.y += wv.z * x.y; a2.z += wv.z * x.z; a2.w += wv.z * x.w;
    }
    *(float4*)&part_sh[w][0][lane * 4] = a0;
    *(float4*)&part_sh[w][1][lane * 4] = a1;
    *(float4*)&part_sh[w][2][lane * 4] = a2;
    __syncthreads();

    // ---- cross-warp sum: 96 threads, float4 wide ----
    if (t < 96) {
        int j = t >> 5;
        int c = (t & 31) * 4;
        float4 s0 = *(const float4*)&part_sh[0][j][c];
        float4 s1 = *(const float4*)&part_sh[1][j][c];
        float4 s2 = *(const float4*)&part_sh[2][j][c];
        float4 s3 = *(const float4*)&part_sh[3][j][c];
        float4 s;
        s.x = (s0.x + s1.x) + (s2.x + s3.x);
        s.y = (s0.y + s1.y) + (s2.y + s3.y);
        s.z = (s0.z + s1.z) + (s2.z + s3.z);
        s.w = (s0.w + s1.w) + (s2.w + s3.w);
        *(float4*)(g_G + (size_t)b * KDIM + j * DIM + c) = s;
    }
}

// ============================================================
// Kernel 2: split-K GEMM, double-buffered.
//   P[j] = G_j (8192x128) @ W_j (128x128); 4 K-stages.
// ============================================================
__global__ __launch_bounds__(256) void gemm_split_kernel(const float* __restrict__ W) {
    __shared__ __align__(16) float Gst[2][32][68];   // [buf][kk][row], transposed
    __shared__ __align__(16) float Ws[2][32][132];   // [buf][kk][col]

    const int tid  = threadIdx.x;
    const int w    = tid >> 5;
    const int lane = tid & 31;
    const int row0 = blockIdx.x * 64;
    const int j    = blockIdx.y;

    const float* Gsrc = g_G + (size_t)row0 * KDIM + j * 128;
    const float* Wsrc = W + (size_t)j * (DIM * DIM);

    float2 acc[8][2];
    #pragma unroll
    for (int i = 0; i < 8; i++) { acc[i][0] = make_float2(0.f, 0.f); acc[i][1] = make_float2(0.f, 0.f); }

    // stage 0 load
    {
        #pragma unroll
        for (int v = 0; v < 2; v++) {
            int f = tid + v * 256;
            int r = f >> 3, c = (f & 7) * 4;
            float4 x = *(const float4*)(Gsrc + (size_t)r * KDIM + c);
            Gst[0][c + 0][r] = x.x; Gst[0][c + 1][r] = x.y;
            Gst[0][c + 2][r] = x.z; Gst[0][c + 3][r] = x.w;
        }
        #pragma unroll
        for (int v = 0; v < 4; v++) {
            int f = tid + v * 256;
            *(float4*)&Ws[0][f >> 5][(f & 31) * 4] =
                *(const float4*)(Wsrc + (size_t)(f >> 5) * DIM + (f & 31) * 4);
        }
    }
    __syncthreads();

    #pragma unroll 1
    for (int s = 0; s < 4; s++) {
        const int cur = s & 1;
        const int nxt = cur ^ 1;

        // prefetch stage s+1 into registers
        float4 gx[2], wx[4];
        if (s < 3) {
            int k0 = (s + 1) * 32;
            #pragma unroll
            for (int v = 0; v < 2; v++) {
                int f = tid + v * 256;
                gx[v] = *(const float4*)(Gsrc + (size_t)(f >> 3) * KDIM + k0 + (f & 7) * 4);
            }
            #pragma unroll
            for (int v = 0; v < 4; v++) {
                int f = tid + v * 256;
                wx[v] = *(const float4*)(Wsrc + (size_t)(k0 + (f >> 5)) * DIM + (f & 31) * 4);
            }
        }

        // compute stage s
        #pragma unroll
        for (int kk = 0; kk < 32; kk++) {
            float4 bv = *(const float4*)&Ws[cur][kk][lane * 4];
            float4 ga = *(const float4*)&Gst[cur][kk][w * 8];
            float4 gb = *(const float4*)&Gst[cur][kk][w * 8 + 4];
            float2 b01 = make_float2(bv.x, bv.y);
            float2 b23 = make_float2(bv.z, bv.w);
            float gs[8] = {ga.x, ga.y, ga.z, ga.w, gb.x, gb.y, gb.z, gb.w};
            #pragma unroll
            for (int i = 0; i < 8; i++) {
                float2 a2 = make_float2(gs[i], gs[i]);
                acc[i][0] = ffma2(a2, b01, acc[i][0]);
                acc[i][1] = ffma2(a2, b23, acc[i][1]);
            }
        }

        // store stage s+1
        if (s < 3) {
            #pragma unroll
            for (int v = 0; v < 2; v++) {
                int f = tid + v * 256;
                int r = f >> 3, c = (f & 7) * 4;
                Gst[nxt][c + 0][r] = gx[v].x; Gst[nxt][c + 1][r] = gx[v].y;
                Gst[nxt][c + 2][r] = gx[v].z; Gst[nxt][c + 3][r] = gx[v].w;
            }
            #pragma unroll
            for (int v = 0; v < 4; v++) {
                int f = tid + v * 256;
                *(float4*)&Ws[nxt][f >> 5][(f & 31) * 4] = wx[v];
            }
        }
        __syncthreads();
    }

    float* Pj = g_P + (size_t)j * (BATCH * DIM);
    #pragma unroll
    for (int i = 0; i < 8; i++) {
        int r = row0 + w * 8 + i;
        float4 v;
        v.x = acc[i][0].x; v.y = acc[i][0].y; v.z = acc[i][1].x; v.w = acc[i][1].y;
        *(float4*)(Pj + (size_t)r * DIM + lane * 4) = v;
    }
}

// ============================================================
// Kernel 3: out = elu(P0 + P1 + P2); 2 float4 per thread
// ============================================================
__global__ __launch_bounds__(256) void epilogue_kernel(float* __restrict__ out) {
    int i0 = (blockIdx.x * 512 + threadIdx.x) * 4;
    int i1 = i0 + 1024;
    float4 a0 = *(const float4*)(g_P + i0);
    float4 b0 = *(const float4*)(g_P + BATCH * DIM + i0);
    float4 c0 = *(const float4*)(g_P + 2 * BATCH * DIM + i0);
    float4 a1 = *(const float4*)(g_P + i1);
    float4 b1 = *(const float4*)(g_P + BATCH * DIM + i1);
    float4 c1 = *(const float4*)(g_P + 2 * BATCH * DIM + i1);
    float4 v0, v1;
    v0.x = a0.x + b0.x + c0.x;  v0.y = a0.y + b0.y + c0.y;
    v0.z = a0.z + b0.z + c0.z;  v0.w = a0.w + b0.w + c0.w;
    v1.x = a1.x + b1.x + c1.x;  v1.y = a1.y + b1.y + c1.y;
    v1.z = a1.z + b1.z + c1.z;  v1.w = a1.w + b1.w + c1.w;
    v0.x = (v0.x > 0.f) ? v0.x : expm1f(v0.x);
    v0.y = (v0.y > 0.f) ? v0.y : expm1f(v0.y);
    v0.z = (v0.z > 0.f) ? v0.z : expm1f(v0.z);
    v0.w = (v0.w > 0.f) ? v0.w : expm1f(v0.w);
    v1.x = (v1.x > 0.f) ? v1.x : expm1f(v1.x);
    v1.y = (v1.y > 0.f) ? v1.y : expm1f(v1.y);
    v1.z = (v1.z > 0.f) ? v1.z : expm1f(v1.z);
    v1.w = (v1.w > 0.f) ? v1.w : expm1f(v1.w);
    *(float4*)(out + i0) = v0;
    *(float4*)(out + i1) = v1;
}

// ============================================================
extern "C" void kernel_launch(void* const* d_in, const int* in_sizes, int n_in,
                              void* d_out, int out_size) {
    const float* h    = (const float*)d_in[0];
    const void*  mask = d_in[1];
    const float* W    = (const float*)d_in[5];
    const float* a    = (const float*)d_in[6];
    float* out = (float*)d_out;

    prep_detect_kernel<<<25, 256>>>((const unsigned int*)mask, W, a);
    attn_kernel<<<BATCH, 128>>>(h, mask);
    gemm_split_kernel<<<dim3(128, 3), 256>>>(W);
    epilogue_kernel<<<(BATCH * DIM) / 2048, 256>>>(out);
}